// round 2
// baseline (speedup 1.0000x reference)
#include <cuda_runtime.h>

#define N_NODES 100000
#define N_EDGES 800000
#define K_DIM   128

// -------- scratch (device globals; no allocation allowed) --------
__device__ __align__(16) float g_deg [N_NODES];
__device__ __align__(16) float g_dinv[N_NODES];
__device__ __align__(16) float g_t  [N_NODES * 128];
__device__ __align__(16) float g_h1 [N_NODES * 128];
__device__ __align__(16) float g_h2 [N_NODES * 128];
__device__ __align__(16) int   g_src[N_EDGES];
__device__ __align__(16) int   g_dst[N_EDGES];
__device__ int g_is64;

// -------- edge index dtype detection + conversion --------
// If the buffer is really int64 (little-endian), the high word of every value
// is 0 (node ids < 2^31). If it is int32, words 1,3,5,... are random src ids,
// essentially never all zero across 64 samples.
__global__ void detect_kernel(const int* __restrict__ ei32) {
    __shared__ int acc;
    if (threadIdx.x == 0) acc = 0;
    __syncthreads();
    int v = ei32[2 * threadIdx.x + 1];
    atomicOr(&acc, v);
    __syncthreads();
    if (threadIdx.x == 0) g_is64 = (acc == 0) ? 1 : 0;
}

__global__ void convert_kernel(const int* __restrict__ ei32,
                               int* __restrict__ src, int* __restrict__ dst) {
    int e = blockIdx.x * blockDim.x + threadIdx.x;
    if (e >= N_EDGES) return;
    if (g_is64) {
        src[e] = ei32[2 * e];
        dst[e] = ei32[2 * (N_EDGES + e)];
    } else {
        src[e] = ei32[e];
        dst[e] = ei32[N_EDGES + e];
    }
}

// -------- degree / normalization --------
__global__ void deg_init_kernel(float* __restrict__ deg) {
    int i = blockIdx.x * blockDim.x + threadIdx.x;
    if (i < N_NODES) deg[i] = 1.0f;   // self-loop
}

__global__ void deg_count_kernel(const int* __restrict__ dst, float* __restrict__ deg) {
    int e = blockIdx.x * blockDim.x + threadIdx.x;
    if (e < N_EDGES) atomicAdd(&deg[dst[e]], 1.0f);
}

__global__ void dinv_kernel(const float* __restrict__ deg, float* __restrict__ dinv) {
    int i = blockIdx.x * blockDim.x + threadIdx.x;
    if (i < N_NODES) dinv[i] = rsqrtf(deg[i]);
}

// -------- GEMM: T = relu?(A) @ W ; OUT = T * dinv[row]^2 + bias --------
// A: [M, 128] row-major. W: [128, BN] row-major. T/OUT: [M, BN].
template <int BN, int TN, bool RELU>
__global__ __launch_bounds__(256)
void gemm_kernel(const float* __restrict__ A, const float* __restrict__ W,
                 const float* __restrict__ bias, const float* __restrict__ dinv,
                 float* __restrict__ T, float* __restrict__ OUT)
{
    constexpr int BM = 128, BK = 8, TM = 8;
    constexpr int TX = BN / TN;              // threads along N (16)
    __shared__ __align__(16) float As[BK][BM];
    __shared__ __align__(16) float Bs[BK][BN];

    const int tid       = threadIdx.x;
    const int block_row = blockIdx.x * BM;
    const int tx        = tid % TX;
    const int ty        = tid / TX;

    float acc[TM][TN];
    #pragma unroll
    for (int i = 0; i < TM; i++)
        #pragma unroll
        for (int j = 0; j < TN; j++) acc[i][j] = 0.0f;

    // A tile load mapping: 128x8 floats = 256 float4 loads (1 per thread)
    const int a_row = tid >> 1;
    const int a_col = (tid & 1) * 4;
    int a_grow = block_row + a_row;
    if (a_grow >= N_NODES) a_grow = N_NODES - 1;      // clamp; store is guarded
    const float* Aptr = A + (size_t)a_grow * K_DIM + a_col;

    // B tile load mapping: 8xBN floats
    constexpr int BLOADS = (BK * BN) / 4;             // 256 (BN=128) or 128 (BN=64)
    const int b_row = tid / (BN / 4);
    const int b_col = (tid % (BN / 4)) * 4;

    for (int k0 = 0; k0 < K_DIM; k0 += BK) {
        float4 av = *reinterpret_cast<const float4*>(Aptr + k0);
        if (RELU) {
            av.x = fmaxf(av.x, 0.0f); av.y = fmaxf(av.y, 0.0f);
            av.z = fmaxf(av.z, 0.0f); av.w = fmaxf(av.w, 0.0f);
        }
        As[a_col + 0][a_row] = av.x;
        As[a_col + 1][a_row] = av.y;
        As[a_col + 2][a_row] = av.z;
        As[a_col + 3][a_row] = av.w;

        if (BLOADS == 256 || tid < BLOADS) {
            float4 bv = *reinterpret_cast<const float4*>(W + (size_t)(k0 + b_row) * BN + b_col);
            *reinterpret_cast<float4*>(&Bs[b_row][b_col]) = bv;
        }
        __syncthreads();

        #pragma unroll
        for (int kk = 0; kk < BK; kk++) {
            float ra[TM], rb[TN];
            #pragma unroll
            for (int i = 0; i < TM; i += 4)
                *reinterpret_cast<float4*>(&ra[i]) =
                    *reinterpret_cast<const float4*>(&As[kk][ty * TM + i]);
            #pragma unroll
            for (int j = 0; j < TN; j += 4)
                *reinterpret_cast<float4*>(&rb[j]) =
                    *reinterpret_cast<const float4*>(&Bs[kk][tx * TN + j]);
            #pragma unroll
            for (int i = 0; i < TM; i++)
                #pragma unroll
                for (int j = 0; j < TN; j++)
                    acc[i][j] = fmaf(ra[i], rb[j], acc[i][j]);
        }
        __syncthreads();
    }

    float bv[TN];
    #pragma unroll
    for (int j = 0; j < TN; j++) bv[j] = bias[tx * TN + j];

    #pragma unroll
    for (int i = 0; i < TM; i++) {
        int row = block_row + ty * TM + i;
        if (row < N_NODES) {
            float dv = dinv[row];
            float sn = dv * dv;
            #pragma unroll
            for (int j = 0; j < TN; j += 4) {
                int col = tx * TN + j;
                float4 tv = make_float4(acc[i][j], acc[i][j + 1], acc[i][j + 2], acc[i][j + 3]);
                *reinterpret_cast<float4*>(T + (size_t)row * BN + col) = tv;
                float4 ov = make_float4(tv.x * sn + bv[j],
                                        tv.y * sn + bv[j + 1],
                                        tv.z * sn + bv[j + 2],
                                        tv.w * sn + bv[j + 3]);
                *reinterpret_cast<float4*>(OUT + (size_t)row * BN + col) = ov;
            }
        }
    }
}

// -------- edge aggregation: OUT[dst] += T[src] * (dinv[src]*dinv[dst]) --------
template <int F>
__global__ __launch_bounds__(256)
void edge_kernel(const int* __restrict__ srcs, const int* __restrict__ dsts,
                 const float* __restrict__ dinv,
                 const float* __restrict__ T, float* __restrict__ OUT)
{
    constexpr int LPE = F / 4;                      // lanes per edge (32 or 16)
    int gid  = blockIdx.x * blockDim.x + threadIdx.x;
    int e    = gid / LPE;
    int lane = gid % LPE;
    if (e >= N_EDGES) return;

    int src = srcs[e];
    int dst = dsts[e];
    float norm = dinv[src] * dinv[dst];

    float4 v = *reinterpret_cast<const float4*>(T + (size_t)src * F + lane * 4);
    float mx = v.x * norm, my = v.y * norm, mz = v.z * norm, mw = v.w * norm;

    float* addr = OUT + (size_t)dst * F + lane * 4;
    asm volatile("red.global.add.v4.f32 [%0], {%1,%2,%3,%4};"
                 :: "l"(addr), "f"(mx), "f"(my), "f"(mz), "f"(mw)
                 : "memory");
}

// -------- launch --------
extern "C" void kernel_launch(void* const* d_in, const int* in_sizes, int n_in,
                              void* d_out, int out_size)
{
    const float* x    = (const float*)d_in[0];
    const int*   ei32 = (const int*)d_in[1];
    const float* W1 = (const float*)d_in[2];
    const float* b1 = (const float*)d_in[3];
    const float* W2 = (const float*)d_in[4];
    const float* b2 = (const float*)d_in[5];
    const float* W3 = (const float*)d_in[6];
    const float* b3 = (const float*)d_in[7];
    float* out = (float*)d_out;

    float *deg, *dinv, *t, *h1, *h2;
    int *src, *dst;
    cudaGetSymbolAddress((void**)&deg,  g_deg);
    cudaGetSymbolAddress((void**)&dinv, g_dinv);
    cudaGetSymbolAddress((void**)&t,    g_t);
    cudaGetSymbolAddress((void**)&h1,   g_h1);
    cudaGetSymbolAddress((void**)&h2,   g_h2);
    cudaGetSymbolAddress((void**)&src,  g_src);
    cudaGetSymbolAddress((void**)&dst,  g_dst);

    const int TB = 256;
    detect_kernel   <<<1, 64>>>(ei32);
    convert_kernel  <<<(N_EDGES + TB - 1) / TB, TB>>>(ei32, src, dst);
    deg_init_kernel <<<(N_NODES + TB - 1) / TB, TB>>>(deg);
    deg_count_kernel<<<(N_EDGES + TB - 1) / TB, TB>>>(dst, deg);
    dinv_kernel     <<<(N_NODES + TB - 1) / TB, TB>>>(deg, dinv);

    dim3 ggrid((N_NODES + 127) / 128);
    int egrid128 = (int)(((long long)N_EDGES * 32 + TB - 1) / TB);   // 32 lanes/edge
    int egrid64  = (int)(((long long)N_EDGES * 16 + TB - 1) / TB);   // 16 lanes/edge

    // Layer 1: h1 = agg(x@W1) + (x@W1)*dinv^2 + b1
    gemm_kernel<128, 8, false><<<ggrid, 256>>>(x,  W1, b1, dinv, t, h1);
    edge_kernel<128>          <<<egrid128, TB>>>(src, dst, dinv, t, h1);

    // Layer 2: relu applied to h1 on load
    gemm_kernel<128, 8, true> <<<ggrid, 256>>>(h1, W2, b2, dinv, t, h2);
    edge_kernel<128>          <<<egrid128, TB>>>(src, dst, dinv, t, h2);

    // Layer 3: output, 64 channels
    gemm_kernel<64, 4, true>  <<<ggrid, 256>>>(h2, W3, b3, dinv, t, out);
    edge_kernel<64>           <<<egrid64, TB>>>(src, dst, dinv, t, out);
}

// round 3
// speedup vs baseline: 1.3886x; 1.3886x over previous
#include <cuda_runtime.h>

#define N_NODES 100000
#define N_EDGES 800000
#define K_DIM   128

// -------- scratch (device globals; no allocation allowed) --------
__device__ __align__(16) float g_dinv [N_NODES];
__device__ __align__(16) float g_t    [N_NODES * 128];
__device__ __align__(16) float g_h1   [N_NODES * 128];
__device__ __align__(16) float g_h2   [N_NODES * 128];
__device__ __align__(16) int   g_src  [N_EDGES];
__device__ __align__(16) int   g_dst  [N_EDGES];
__device__ __align__(16) int   g_csr  [N_EDGES];     // src ids grouped by dst
__device__ __align__(16) int   g_cnt  [N_NODES];     // in-degree (no self loop)
__device__ __align__(16) int   g_start[N_NODES];     // segment start in g_csr
__device__ __align__(16) int   g_cur  [N_NODES];     // scatter cursor
__device__ int g_total;
__device__ int g_is64;

// -------- edge index dtype detection + conversion --------
__global__ void detect_kernel(const int* __restrict__ ei32) {
    __shared__ int acc;
    if (threadIdx.x == 0) acc = 0;
    __syncthreads();
    atomicOr(&acc, ei32[2 * threadIdx.x + 1]);
    __syncthreads();
    if (threadIdx.x == 0) g_is64 = (acc == 0) ? 1 : 0;
}

__global__ void convert_kernel(const int* __restrict__ ei32,
                               int* __restrict__ src, int* __restrict__ dst) {
    int e = blockIdx.x * blockDim.x + threadIdx.x;
    if (e >= N_EDGES) return;
    if (g_is64) {
        src[e] = ei32[2 * e];
        dst[e] = ei32[2 * (N_EDGES + e)];
    } else {
        src[e] = ei32[e];
        dst[e] = ei32[N_EDGES + e];
    }
}

// -------- CSR build --------
__global__ void zero_kernel(int* __restrict__ cnt, int* __restrict__ total) {
    int i = blockIdx.x * blockDim.x + threadIdx.x;
    if (i < N_NODES) cnt[i] = 0;
    if (i == 0) *total = 0;
}

__global__ void hist_kernel(const int* __restrict__ dst, int* __restrict__ cnt) {
    int e = blockIdx.x * blockDim.x + threadIdx.x;
    if (e < N_EDGES) atomicAdd(&cnt[dst[e]], 1);
}

__global__ void dinv_kernel(const int* __restrict__ cnt, float* __restrict__ dinv) {
    int i = blockIdx.x * blockDim.x + threadIdx.x;
    if (i < N_NODES) dinv[i] = rsqrtf((float)cnt[i] + 1.0f);
}

// Assign each node a contiguous segment (order arbitrary — no scan needed).
__global__ void seg_kernel(const int* __restrict__ cnt, int* __restrict__ start,
                           int* __restrict__ cur, int* __restrict__ total) {
    int i = blockIdx.x * blockDim.x + threadIdx.x;
    if (i < N_NODES) {
        int s = atomicAdd(total, cnt[i]);
        start[i] = s;
        cur[i]   = s;
    }
}

__global__ void scatter_kernel(const int* __restrict__ src, const int* __restrict__ dst,
                               int* __restrict__ cur, int* __restrict__ csr) {
    int e = blockIdx.x * blockDim.x + threadIdx.x;
    if (e < N_EDGES) {
        int pos = atomicAdd(&cur[dst[e]], 1);
        csr[pos] = src[e];
    }
}

// -------- GEMM: T = relu?(A) @ W --------
template <int BN, int TN, bool RELU>
__global__ __launch_bounds__(256)
void gemm_kernel(const float* __restrict__ A, const float* __restrict__ W,
                 float* __restrict__ T)
{
    constexpr int BM = 128, BK = 8, TM = 8;
    constexpr int TX = BN / TN;
    __shared__ __align__(16) float As[BK][BM];
    __shared__ __align__(16) float Bs[BK][BN];

    const int tid       = threadIdx.x;
    const int block_row = blockIdx.x * BM;
    const int tx        = tid % TX;
    const int ty        = tid / TX;

    float acc[TM][TN];
    #pragma unroll
    for (int i = 0; i < TM; i++)
        #pragma unroll
        for (int j = 0; j < TN; j++) acc[i][j] = 0.0f;

    const int a_row = tid >> 1;
    const int a_col = (tid & 1) * 4;
    int a_grow = block_row + a_row;
    if (a_grow >= N_NODES) a_grow = N_NODES - 1;
    const float* Aptr = A + (size_t)a_grow * K_DIM + a_col;

    constexpr int BLOADS = (BK * BN) / 4;
    const int b_row = tid / (BN / 4);
    const int b_col = (tid % (BN / 4)) * 4;

    for (int k0 = 0; k0 < K_DIM; k0 += BK) {
        float4 av = *reinterpret_cast<const float4*>(Aptr + k0);
        if (RELU) {
            av.x = fmaxf(av.x, 0.0f); av.y = fmaxf(av.y, 0.0f);
            av.z = fmaxf(av.z, 0.0f); av.w = fmaxf(av.w, 0.0f);
        }
        As[a_col + 0][a_row] = av.x;
        As[a_col + 1][a_row] = av.y;
        As[a_col + 2][a_row] = av.z;
        As[a_col + 3][a_row] = av.w;

        if (BLOADS == 256 || tid < BLOADS) {
            float4 bv = *reinterpret_cast<const float4*>(W + (size_t)(k0 + b_row) * BN + b_col);
            *reinterpret_cast<float4*>(&Bs[b_row][b_col]) = bv;
        }
        __syncthreads();

        #pragma unroll
        for (int kk = 0; kk < BK; kk++) {
            float ra[TM], rb[TN];
            #pragma unroll
            for (int i = 0; i < TM; i += 4)
                *reinterpret_cast<float4*>(&ra[i]) =
                    *reinterpret_cast<const float4*>(&As[kk][ty * TM + i]);
            #pragma unroll
            for (int j = 0; j < TN; j += 4)
                *reinterpret_cast<float4*>(&rb[j]) =
                    *reinterpret_cast<const float4*>(&Bs[kk][tx * TN + j]);
            #pragma unroll
            for (int i = 0; i < TM; i++)
                #pragma unroll
                for (int j = 0; j < TN; j++)
                    acc[i][j] = fmaf(ra[i], rb[j], acc[i][j]);
        }
        __syncthreads();
    }

    #pragma unroll
    for (int i = 0; i < TM; i++) {
        int row = block_row + ty * TM + i;
        if (row < N_NODES) {
            #pragma unroll
            for (int j = 0; j < TN; j += 4) {
                float4 tv = make_float4(acc[i][j], acc[i][j + 1], acc[i][j + 2], acc[i][j + 3]);
                *reinterpret_cast<float4*>(T + (size_t)row * BN + tx * TN + j) = tv;
            }
        }
    }
}

// -------- gather aggregation: OUT[n] = dinv[n]*sum_{s in N(n)} dinv[s]*T[s]
//                                      + dinv[n]^2 * T[n] + b --------
template <int F>
__global__ __launch_bounds__(256)
void agg_kernel(const int* __restrict__ start, const int* __restrict__ cnt,
                const int* __restrict__ csr, const float* __restrict__ dinv,
                const float* __restrict__ T, const float* __restrict__ bias,
                float* __restrict__ OUT)
{
    constexpr int LPN = F / 4;                     // lanes per node (32 or 16)
    int gid  = blockIdx.x * blockDim.x + threadIdx.x;
    int node = gid / LPN;
    int lane = gid % LPN;
    if (node >= N_NODES) return;

    const int s = start[node];
    const int c = cnt[node];
    const int off = lane * 4;

    float4 acc = make_float4(0.f, 0.f, 0.f, 0.f);
    int j = 0;
    for (; j + 4 <= c; j += 4) {
        int s0 = csr[s + j], s1 = csr[s + j + 1], s2 = csr[s + j + 2], s3 = csr[s + j + 3];
        float w0 = dinv[s0], w1 = dinv[s1], w2 = dinv[s2], w3 = dinv[s3];
        float4 v0 = *reinterpret_cast<const float4*>(T + (size_t)s0 * F + off);
        float4 v1 = *reinterpret_cast<const float4*>(T + (size_t)s1 * F + off);
        float4 v2 = *reinterpret_cast<const float4*>(T + (size_t)s2 * F + off);
        float4 v3 = *reinterpret_cast<const float4*>(T + (size_t)s3 * F + off);
        acc.x = fmaf(v0.x, w0, acc.x); acc.y = fmaf(v0.y, w0, acc.y);
        acc.z = fmaf(v0.z, w0, acc.z); acc.w = fmaf(v0.w, w0, acc.w);
        acc.x = fmaf(v1.x, w1, acc.x); acc.y = fmaf(v1.y, w1, acc.y);
        acc.z = fmaf(v1.z, w1, acc.z); acc.w = fmaf(v1.w, w1, acc.w);
        acc.x = fmaf(v2.x, w2, acc.x); acc.y = fmaf(v2.y, w2, acc.y);
        acc.z = fmaf(v2.z, w2, acc.z); acc.w = fmaf(v2.w, w2, acc.w);
        acc.x = fmaf(v3.x, w3, acc.x); acc.y = fmaf(v3.y, w3, acc.y);
        acc.z = fmaf(v3.z, w3, acc.z); acc.w = fmaf(v3.w, w3, acc.w);
    }
    for (; j < c; j++) {
        int s0 = csr[s + j];
        float w0 = dinv[s0];
        float4 v0 = *reinterpret_cast<const float4*>(T + (size_t)s0 * F + off);
        acc.x = fmaf(v0.x, w0, acc.x); acc.y = fmaf(v0.y, w0, acc.y);
        acc.z = fmaf(v0.z, w0, acc.z); acc.w = fmaf(v0.w, w0, acc.w);
    }

    float dv = dinv[node];
    float sn = dv * dv;
    float4 ts = *reinterpret_cast<const float4*>(T + (size_t)node * F + off);
    float4 bv = *reinterpret_cast<const float4*>(bias + off);
    float4 o;
    o.x = fmaf(acc.x, dv, fmaf(ts.x, sn, bv.x));
    o.y = fmaf(acc.y, dv, fmaf(ts.y, sn, bv.y));
    o.z = fmaf(acc.z, dv, fmaf(ts.z, sn, bv.z));
    o.w = fmaf(acc.w, dv, fmaf(ts.w, sn, bv.w));
    *reinterpret_cast<float4*>(OUT + (size_t)node * F + off) = o;
}

// -------- launch --------
extern "C" void kernel_launch(void* const* d_in, const int* in_sizes, int n_in,
                              void* d_out, int out_size)
{
    const float* x    = (const float*)d_in[0];
    const int*   ei32 = (const int*)d_in[1];
    const float* W1 = (const float*)d_in[2];
    const float* b1 = (const float*)d_in[3];
    const float* W2 = (const float*)d_in[4];
    const float* b2 = (const float*)d_in[5];
    const float* W3 = (const float*)d_in[6];
    const float* b3 = (const float*)d_in[7];
    float* out = (float*)d_out;

    float *dinv, *t, *h1, *h2;
    int *src, *dst, *csr, *cnt, *start, *cur, *total;
    cudaGetSymbolAddress((void**)&dinv,  g_dinv);
    cudaGetSymbolAddress((void**)&t,     g_t);
    cudaGetSymbolAddress((void**)&h1,    g_h1);
    cudaGetSymbolAddress((void**)&h2,    g_h2);
    cudaGetSymbolAddress((void**)&src,   g_src);
    cudaGetSymbolAddress((void**)&dst,   g_dst);
    cudaGetSymbolAddress((void**)&csr,   g_csr);
    cudaGetSymbolAddress((void**)&cnt,   g_cnt);
    cudaGetSymbolAddress((void**)&start, g_start);
    cudaGetSymbolAddress((void**)&cur,   g_cur);
    cudaGetSymbolAddress((void**)&total, g_total);

    const int TB = 256;
    const int NGRID = (N_NODES + TB - 1) / TB;
    const int EGRID = (N_EDGES + TB - 1) / TB;

    detect_kernel  <<<1, 64>>>(ei32);
    convert_kernel <<<EGRID, TB>>>(ei32, src, dst);
    zero_kernel    <<<NGRID, TB>>>(cnt, total);
    hist_kernel    <<<EGRID, TB>>>(dst, cnt);
    dinv_kernel    <<<NGRID, TB>>>(cnt, dinv);
    seg_kernel     <<<NGRID, TB>>>(cnt, start, cur, total);
    scatter_kernel <<<EGRID, TB>>>(src, dst, cur, csr);

    dim3 ggrid((N_NODES + 127) / 128);
    const int agrid128 = (N_NODES * 32 + TB - 1) / TB;
    const int agrid64  = (N_NODES * 16 + TB - 1) / TB;

    // Layer 1
    gemm_kernel<128, 8, false><<<ggrid, 256>>>(x, W1, t);
    agg_kernel<128><<<agrid128, TB>>>(start, cnt, csr, dinv, t, b1, h1);
    // Layer 2 (relu on load)
    gemm_kernel<128, 8, true><<<ggrid, 256>>>(h1, W2, t);
    agg_kernel<128><<<agrid128, TB>>>(start, cnt, csr, dinv, t, b2, h2);
    // Layer 3 (64 channels)
    gemm_kernel<64, 4, true><<<ggrid, 256>>>(h2, W3, t);
    agg_kernel<64><<<agrid64, TB>>>(start, cnt, csr, dinv, t, b3, out);
}